// round 12
// baseline (speedup 1.0000x reference)
#include <cuda_runtime.h>
#include <cuda_fp16.h>
#include <math.h>

#define NN 100000
#define NE 3200000

// Scratch (static device globals — zero-initialized at module load; kernels
// restore the zero state each run so no init kernel is needed).
__device__ int    g_src[NE];    // int64-fallback only
__device__ int    g_dst[NE];    // int64-fallback only
__device__ __half g_w16[NE];    // fp16 weight cache (6.4MB)
__device__ float  g_degx[NN];   // EXTRA degree (beyond self-loop); reset by k_dinv
__device__ float  g_dinv[NN];
__device__ __half g_p1[NN];     // half(dinv * x)
__device__ float  g_acc1[NN];   // reset by k_node_mid after reading
__device__ __half g_gd[NN];     // half(dinv * (g1-g0))
__device__ float  g_acc2[NN];   // seeded by store in k_node_mid (no init needed)

__device__ __forceinline__ int clampn(int v) { return min(max(v, 0), NN - 1); }

// Per-block dtype probe: OR 64 odd words of the first 256B of the edge buffer.
// int64 payload -> high halves of src[0..31] -> all zero. int32 payload ->
// random node ids -> nonzero (w.p. 1 - 1e-160). L2-hot after the first block.
__device__ __forceinline__ bool probe_is_i64(const unsigned* ei32) {
    __shared__ int s_i64;
    if (threadIdx.x < 32) {
        unsigned v = ei32[2 * threadIdx.x + 1];
        #pragma unroll
        for (int off = 16; off > 0; off >>= 1)
            v |= __shfl_xor_sync(0xFFFFFFFFu, v, off);
        if (threadIdx.x == 0) s_i64 = (v == 0u);
    }
    __syncthreads();
    return s_i64 != 0;
}

// ------- edge: degree REDs + fp16 weight cache (+ narrowing if int64) -------
__global__ void k_deg(const void* __restrict__ eiv,
                      const float* __restrict__ w) {
    bool i64 = probe_is_i64((const unsigned*)eiv);
    int e = (blockIdx.x * blockDim.x + threadIdx.x) * 8;
    if (e >= NE) return;
    if (!i64) {                               // int32 payload
        const int* dp = (const int*)eiv + NE;
        float4 wa = __ldcs((const float4*)(w + e));
        float4 wb = __ldcs((const float4*)(w + e + 4));
        __half2 h0 = __floats2half2_rn(wa.x, wa.y);
        __half2 h1 = __floats2half2_rn(wa.z, wa.w);
        __half2 h2 = __floats2half2_rn(wb.x, wb.y);
        __half2 h3 = __floats2half2_rn(wb.z, wb.w);
        *(uint4*)(g_w16 + e) = make_uint4(*(unsigned*)&h0, *(unsigned*)&h1,
                                          *(unsigned*)&h2, *(unsigned*)&h3);
        int4 da = __ldcs((const int4*)(dp + e));
        int4 db = __ldcs((const int4*)(dp + e + 4));
        atomicAdd(&g_degx[clampn(da.x)], wa.x);
        atomicAdd(&g_degx[clampn(da.y)], wa.y);
        atomicAdd(&g_degx[clampn(da.z)], wa.z);
        atomicAdd(&g_degx[clampn(da.w)], wa.w);
        atomicAdd(&g_degx[clampn(db.x)], wb.x);
        atomicAdd(&g_degx[clampn(db.y)], wb.y);
        atomicAdd(&g_degx[clampn(db.z)], wb.z);
        atomicAdd(&g_degx[clampn(db.w)], wb.w);
    } else {                                  // int64 fallback: narrow + stash
        const long long* ei = (const long long*)eiv;
        #pragma unroll
        for (int k = 0; k < 8; k++) {
            int s = clampn((int)ei[e + k]);
            int d = clampn((int)ei[NE + e + k]);
            float wk = w[e + k];
            g_src[e + k] = s;  g_dst[e + k] = d;
            g_w16[e + k] = __float2half_rn(wk);
            atomicAdd(&g_degx[d], wk);
        }
    }
}

// ------------- node: dinv + pre-scaled feature; resets g_degx ---------------
__global__ void k_dinv(const float* __restrict__ x) {
    int n = blockIdx.x * blockDim.x + threadIdx.x;
    if (n < NN) {
        float d  = g_degx[n] + 1.0f;            // + self-loop weight
        g_degx[n] = 0.0f;                        // restore zero state for next run
        float di = rsqrtf(d);                    // d >= 1 always
        g_dinv[n] = di;
        g_p1[n]   = __float2half_rn(di * x[n]);
    }
}

// -------------------- edge: layer-1 aggregation  acc1[d] += w * p1[s] -------
__global__ void k_scatter1(const void* __restrict__ eiv) {
    bool i64 = probe_is_i64((const unsigned*)eiv);
    int e = (blockIdx.x * blockDim.x + threadIdx.x) * 8;
    if (e >= NE) return;
    const int* sp; const int* dp;
    if (!i64) { sp = (const int*)eiv; dp = sp + NE; }
    else      { sp = g_src;           dp = g_dst;   }
    int4  sa = __ldcs((const int4*)(sp + e));
    int4  sb = __ldcs((const int4*)(sp + e + 4));
    int4  da = __ldcs((const int4*)(dp + e));
    int4  db = __ldcs((const int4*)(dp + e + 4));
    uint4 wp = __ldcs((const uint4*)(g_w16 + e));
    float2 w01 = __half22float2(*(__half2*)&wp.x);
    float2 w23 = __half22float2(*(__half2*)&wp.y);
    float2 w45 = __half22float2(*(__half2*)&wp.z);
    float2 w67 = __half22float2(*(__half2*)&wp.w);
    float p0 = __half2float(__ldg(&g_p1[clampn(sa.x)]));
    float p1 = __half2float(__ldg(&g_p1[clampn(sa.y)]));
    float p2 = __half2float(__ldg(&g_p1[clampn(sa.z)]));
    float p3 = __half2float(__ldg(&g_p1[clampn(sa.w)]));
    float p4 = __half2float(__ldg(&g_p1[clampn(sb.x)]));
    float p5 = __half2float(__ldg(&g_p1[clampn(sb.y)]));
    float p6 = __half2float(__ldg(&g_p1[clampn(sb.z)]));
    float p7 = __half2float(__ldg(&g_p1[clampn(sb.w)]));
    atomicAdd(&g_acc1[clampn(da.x)], w01.x * p0);
    atomicAdd(&g_acc1[clampn(da.y)], w01.y * p1);
    atomicAdd(&g_acc1[clampn(da.z)], w23.x * p2);
    atomicAdd(&g_acc1[clampn(da.w)], w23.y * p3);
    atomicAdd(&g_acc1[clampn(db.x)], w45.x * p4);
    atomicAdd(&g_acc1[clampn(db.y)], w45.y * p5);
    atomicAdd(&g_acc1[clampn(db.z)], w67.x * p6);
    atomicAdd(&g_acc1[clampn(db.w)], w67.y * p7);
}

// ---- node: finish layer-1, dense, delta-projection; resets g_acc1 ----------
__global__ void k_node_mid(const float* __restrict__ x,
                           const float* __restrict__ W1,
                           const float* __restrict__ b1,
                           const float* __restrict__ W2) {
    int n = blockIdx.x * blockDim.x + threadIdx.x;
    if (n < NN) {
        float di = g_dinv[n];
        float a1 = g_acc1[n];
        g_acc1[n] = 0.0f;                        // restore zero state
        float sv = di * (a1 + di * x[n]);
        float g0 = 0.0f, g1 = 0.0f;
        #pragma unroll
        for (int j = 0; j < 16; j++) {
            float h = fmaxf(fmaf(sv, __ldg(&W1[j]), __ldg(&b1[j])), 0.0f);
            g0 = fmaf(h, __ldg(&W2[2 * j    ]), g0);
            g1 = fmaf(h, __ldg(&W2[2 * j + 1]), g1);
        }
        float gd = di * (g1 - g0);     // only the class difference matters
        g_gd[n]   = __float2half_rn(gd);
        g_acc2[n] = gd;                // self-loop seed (plain store, no init)
    }
}

// ------------- edge: layer-2 aggregation (scalar)  acc2[d] += w * gd[s] -----
__global__ void k_scatter2(const void* __restrict__ eiv) {
    bool i64 = probe_is_i64((const unsigned*)eiv);
    int e = (blockIdx.x * blockDim.x + threadIdx.x) * 8;
    if (e >= NE) return;
    const int* sp; const int* dp;
    if (!i64) { sp = (const int*)eiv; dp = sp + NE; }
    else      { sp = g_src;           dp = g_dst;   }
    int4  sa = __ldcs((const int4*)(sp + e));
    int4  sb = __ldcs((const int4*)(sp + e + 4));
    int4  da = __ldcs((const int4*)(dp + e));
    int4  db = __ldcs((const int4*)(dp + e + 4));
    uint4 wp = __ldcs((const uint4*)(g_w16 + e));
    float2 w01 = __half22float2(*(__half2*)&wp.x);
    float2 w23 = __half22float2(*(__half2*)&wp.y);
    float2 w45 = __half22float2(*(__half2*)&wp.z);
    float2 w67 = __half22float2(*(__half2*)&wp.w);
    float v0 = __half2float(__ldg(&g_gd[clampn(sa.x)]));
    float v1 = __half2float(__ldg(&g_gd[clampn(sa.y)]));
    float v2 = __half2float(__ldg(&g_gd[clampn(sa.z)]));
    float v3 = __half2float(__ldg(&g_gd[clampn(sa.w)]));
    float v4 = __half2float(__ldg(&g_gd[clampn(sb.x)]));
    float v5 = __half2float(__ldg(&g_gd[clampn(sb.y)]));
    float v6 = __half2float(__ldg(&g_gd[clampn(sb.z)]));
    float v7 = __half2float(__ldg(&g_gd[clampn(sb.w)]));
    atomicAdd(&g_acc2[clampn(da.x)], w01.x * v0);
    atomicAdd(&g_acc2[clampn(da.y)], w01.y * v1);
    atomicAdd(&g_acc2[clampn(da.z)], w23.x * v2);
    atomicAdd(&g_acc2[clampn(da.w)], w23.y * v3);
    atomicAdd(&g_acc2[clampn(db.x)], w45.x * v4);
    atomicAdd(&g_acc2[clampn(db.y)], w45.y * v5);
    atomicAdd(&g_acc2[clampn(db.z)], w67.x * v6);
    atomicAdd(&g_acc2[clampn(db.w)], w67.y * v7);
}

// -------------- node: delta -> 2-way log_softmax ----------------------------
__global__ void k_out(const float* __restrict__ b2, float2* __restrict__ out) {
    int n = blockIdx.x * blockDim.x + threadIdx.x;
    if (n < NN) {
        float di = g_dinv[n];
        float v  = di * g_acc2[n] + (__ldg(&b2[1]) - __ldg(&b2[0]));  // v1-v0
        float o0 = (v > 0.0f) ? (-v - log1pf(expf(-v))) : (-log1pf(expf(v)));
        out[n] = make_float2(o0, o0 + v);
    }
}

extern "C" void kernel_launch(void* const* d_in, const int* in_sizes, int n_in,
                              void* d_out, int out_size) {
    const float* x = 0; const void* ei = 0; const float* w = 0;
    const float* W1 = 0; const float* b1 = 0; const float* W2 = 0; const float* b2 = 0;
    for (int i = 0; i < n_in; i++) {
        int sz = in_sizes[i];
        if      (sz == NN)     x  = (const float*)d_in[i];
        else if (sz == 2 * NE) ei = d_in[i];
        else if (sz == NE)     w  = (const float*)d_in[i];
        else if (sz == 32)     W2 = (const float*)d_in[i];
        else if (sz == 2)      b2 = (const float*)d_in[i];
        else if (sz == 16) {
            if (!W1) W1 = (const float*)d_in[i];
            else     b1 = (const float*)d_in[i];
        }
    }

    const int TB = 256;
    const int GN = (NN + TB - 1) / TB;
    const int GE = (NE / 8 + TB - 1) / TB;   // NE % 8 == 0

    k_deg       <<<GE, TB>>>(ei, w);
    k_dinv      <<<GN, TB>>>(x);
    k_scatter1  <<<GE, TB>>>(ei);
    k_node_mid  <<<GN, TB>>>(x, W1, b1, W2);
    k_scatter2  <<<GE, TB>>>(ei);
    k_out       <<<GN, TB>>>(b2, (float2*)d_out);
}

// round 13
// speedup vs baseline: 1.2247x; 1.2247x over previous
#include <cuda_runtime.h>
#include <cuda_fp16.h>
#include <math.h>

#define NN 100000
#define NE 3200000

// Scratch (static device globals — no allocs anywhere)
__device__ int    g_src[NE];    // int64-fallback only
__device__ int    g_dst[NE];    // int64-fallback only
__device__ __half g_w16[NE];    // fp16 weight cache (6.4MB)
__device__ float  g_deg[NN];
__device__ float  g_dinv[NN];
__device__ __half g_p1[NN];     // half(dinv * x)
__device__ float  g_acc1[NN];   // zeroed in k_dinv (pre-scatter1)
__device__ __half g_gd[NN];     // half(dinv * (g1-g0))
__device__ float  g_acc2[NN];   // seeded by store in k_node_mid
__device__ unsigned g_hi_or;    // 0 => int64 edge_index

__device__ __forceinline__ int clampn(int v) { return min(max(v, 0), NN - 1); }

// gather load pinned into L1 (evict_last); streams use ld.global.cs
__device__ __forceinline__ float ldg_h_pin(const __half* p) {
    unsigned short u;
    asm volatile("ld.global.nc.L1::evict_last.u16 %0, [%1];" : "=h"(u) : "l"(p));
    return __half2float(__ushort_as_half(u));
}

// ------------------- node init (deg only) + dtype probe ---------------------
__global__ void k_init(const unsigned int* __restrict__ ei32) {
    int n = blockIdx.x * blockDim.x + threadIdx.x;
    if (n == 0) g_hi_or = 0u;
    if (n < NN) g_deg[n] = 1.0f;   // self-loop weight
    if (blockIdx.x == 0) {         // sample 2048 odd words (0 iff int64 payload)
        unsigned v = 0u;
        #pragma unroll
        for (int k = 0; k < 8; k++) v |= ei32[2 * (threadIdx.x * 8 + k) + 1];
        #pragma unroll
        for (int off = 16; off > 0; off >>= 1)
            v |= __shfl_xor_sync(0xFFFFFFFFu, v, off);
        if ((threadIdx.x & 31) == 0 && v) atomicOr(&g_hi_or, v);
    }
}

// ------- edge: degree REDs + fp16 weight cache (+ narrowing if int64) -------
__global__ void k_deg(const void* __restrict__ eiv,
                      const float* __restrict__ w) {
    int e = (blockIdx.x * blockDim.x + threadIdx.x) * 8;
    if (e >= NE) return;
    float4 wa = __ldcs((const float4*)(w + e));
    float4 wb = __ldcs((const float4*)(w + e + 4));
    __half2 h0 = __floats2half2_rn(wa.x, wa.y);
    __half2 h1 = __floats2half2_rn(wa.z, wa.w);
    __half2 h2 = __floats2half2_rn(wb.x, wb.y);
    __half2 h3 = __floats2half2_rn(wb.z, wb.w);
    *(uint4*)(g_w16 + e) = make_uint4(*(unsigned*)&h0, *(unsigned*)&h1,
                                      *(unsigned*)&h2, *(unsigned*)&h3);
    if (g_hi_or != 0u) {                      // int32 payload
        const int* dp = (const int*)eiv + NE;
        int4 da = __ldcs((const int4*)(dp + e));
        int4 db = __ldcs((const int4*)(dp + e + 4));
        atomicAdd(&g_deg[clampn(da.x)], wa.x);
        atomicAdd(&g_deg[clampn(da.y)], wa.y);
        atomicAdd(&g_deg[clampn(da.z)], wa.z);
        atomicAdd(&g_deg[clampn(da.w)], wa.w);
        atomicAdd(&g_deg[clampn(db.x)], wb.x);
        atomicAdd(&g_deg[clampn(db.y)], wb.y);
        atomicAdd(&g_deg[clampn(db.z)], wb.z);
        atomicAdd(&g_deg[clampn(db.w)], wb.w);
    } else {                                  // int64 fallback: narrow + stash
        const long long* ei = (const long long*)eiv;
        #pragma unroll
        for (int k = 0; k < 8; k++) {
            int s = clampn((int)ei[e + k]);
            int d = clampn((int)ei[NE + e + k]);
            float wk = (k < 4) ? (&wa.x)[k] : (&wb.x)[k - 4];
            g_src[e + k] = s;  g_dst[e + k] = d;
            atomicAdd(&g_deg[d], wk);
        }
    }
}

// ------- node: dinv + pre-scaled feature; zeroes acc1 for scatter1 ----------
__global__ void k_dinv(const float* __restrict__ x) {
    int n = blockIdx.x * blockDim.x + threadIdx.x;
    if (n < NN) {
        float d  = g_deg[n];
        float di = (d > 0.0f) ? rsqrtf(d) : 0.0f;
        g_dinv[n] = di;
        g_p1[n]   = __float2half_rn(di * x[n]);
        g_acc1[n] = 0.0f;
    }
}

// -------------------- edge: layer-1 aggregation  acc1[d] += w * p1[s] -------
__global__ void k_scatter1(const void* __restrict__ eiv) {
    int e = (blockIdx.x * blockDim.x + threadIdx.x) * 8;
    if (e >= NE) return;
    const int* sp; const int* dp;
    if (g_hi_or != 0u) { sp = (const int*)eiv; dp = sp + NE; }
    else               { sp = g_src;           dp = g_dst;   }
    int4  sa = __ldcs((const int4*)(sp + e));
    int4  sb = __ldcs((const int4*)(sp + e + 4));
    int4  da = __ldcs((const int4*)(dp + e));
    int4  db = __ldcs((const int4*)(dp + e + 4));
    uint4 wp = __ldcs((const uint4*)(g_w16 + e));
    float2 w01 = __half22float2(*(__half2*)&wp.x);
    float2 w23 = __half22float2(*(__half2*)&wp.y);
    float2 w45 = __half22float2(*(__half2*)&wp.z);
    float2 w67 = __half22float2(*(__half2*)&wp.w);
    float p0 = ldg_h_pin(&g_p1[clampn(sa.x)]);
    float p1 = ldg_h_pin(&g_p1[clampn(sa.y)]);
    float p2 = ldg_h_pin(&g_p1[clampn(sa.z)]);
    float p3 = ldg_h_pin(&g_p1[clampn(sa.w)]);
    float p4 = ldg_h_pin(&g_p1[clampn(sb.x)]);
    float p5 = ldg_h_pin(&g_p1[clampn(sb.y)]);
    float p6 = ldg_h_pin(&g_p1[clampn(sb.z)]);
    float p7 = ldg_h_pin(&g_p1[clampn(sb.w)]);
    atomicAdd(&g_acc1[clampn(da.x)], w01.x * p0);
    atomicAdd(&g_acc1[clampn(da.y)], w01.y * p1);
    atomicAdd(&g_acc1[clampn(da.z)], w23.x * p2);
    atomicAdd(&g_acc1[clampn(da.w)], w23.y * p3);
    atomicAdd(&g_acc1[clampn(db.x)], w45.x * p4);
    atomicAdd(&g_acc1[clampn(db.y)], w45.y * p5);
    atomicAdd(&g_acc1[clampn(db.z)], w67.x * p6);
    atomicAdd(&g_acc1[clampn(db.w)], w67.y * p7);
}

// -------- node: finish layer-1, dense W1/b1/relu/W2, delta-projection -------
__global__ void k_node_mid(const float* __restrict__ x,
                           const float* __restrict__ W1,
                           const float* __restrict__ b1,
                           const float* __restrict__ W2) {
    int n = blockIdx.x * blockDim.x + threadIdx.x;
    if (n < NN) {
        float di = g_dinv[n];
        float sv = di * (g_acc1[n] + di * x[n]);
        float g0 = 0.0f, g1 = 0.0f;
        #pragma unroll
        for (int j = 0; j < 16; j++) {
            float h = fmaxf(fmaf(sv, __ldg(&W1[j]), __ldg(&b1[j])), 0.0f);
            g0 = fmaf(h, __ldg(&W2[2 * j    ]), g0);
            g1 = fmaf(h, __ldg(&W2[2 * j + 1]), g1);
        }
        float gd = di * (g1 - g0);     // only the class difference matters
        g_gd[n]   = __float2half_rn(gd);
        g_acc2[n] = gd;                // self-loop seed
    }
}

// ------------- edge: layer-2 aggregation (scalar)  acc2[d] += w * gd[s] -----
__global__ void k_scatter2(const void* __restrict__ eiv) {
    int e = (blockIdx.x * blockDim.x + threadIdx.x) * 8;
    if (e >= NE) return;
    const int* sp; const int* dp;
    if (g_hi_or != 0u) { sp = (const int*)eiv; dp = sp + NE; }
    else               { sp = g_src;           dp = g_dst;   }
    int4  sa = __ldcs((const int4*)(sp + e));
    int4  sb = __ldcs((const int4*)(sp + e + 4));
    int4  da = __ldcs((const int4*)(dp + e));
    int4  db = __ldcs((const int4*)(dp + e + 4));
    uint4 wp = __ldcs((const uint4*)(g_w16 + e));
    float2 w01 = __half22float2(*(__half2*)&wp.x);
    float2 w23 = __half22float2(*(__half2*)&wp.y);
    float2 w45 = __half22float2(*(__half2*)&wp.z);
    float2 w67 = __half22float2(*(__half2*)&wp.w);
    float v0 = ldg_h_pin(&g_gd[clampn(sa.x)]);
    float v1 = ldg_h_pin(&g_gd[clampn(sa.y)]);
    float v2 = ldg_h_pin(&g_gd[clampn(sa.z)]);
    float v3 = ldg_h_pin(&g_gd[clampn(sa.w)]);
    float v4 = ldg_h_pin(&g_gd[clampn(sb.x)]);
    float v5 = ldg_h_pin(&g_gd[clampn(sb.y)]);
    float v6 = ldg_h_pin(&g_gd[clampn(sb.z)]);
    float v7 = ldg_h_pin(&g_gd[clampn(sb.w)]);
    atomicAdd(&g_acc2[clampn(da.x)], w01.x * v0);
    atomicAdd(&g_acc2[clampn(da.y)], w01.y * v1);
    atomicAdd(&g_acc2[clampn(da.z)], w23.x * v2);
    atomicAdd(&g_acc2[clampn(da.w)], w23.y * v3);
    atomicAdd(&g_acc2[clampn(db.x)], w45.x * v4);
    atomicAdd(&g_acc2[clampn(db.y)], w45.y * v5);
    atomicAdd(&g_acc2[clampn(db.z)], w67.x * v6);
    atomicAdd(&g_acc2[clampn(db.w)], w67.y * v7);
}

// -------------- node: delta -> 2-way log_softmax ----------------------------
__global__ void k_out(const float* __restrict__ b2, float2* __restrict__ out) {
    int n = blockIdx.x * blockDim.x + threadIdx.x;
    if (n < NN) {
        float di = g_dinv[n];
        float v  = di * g_acc2[n] + (__ldg(&b2[1]) - __ldg(&b2[0]));  // v1-v0
        float o0 = (v > 0.0f) ? (-v - log1pf(expf(-v))) : (-log1pf(expf(v)));
        out[n] = make_float2(o0, o0 + v);
    }
}

extern "C" void kernel_launch(void* const* d_in, const int* in_sizes, int n_in,
                              void* d_out, int out_size) {
    const float* x = 0; const void* ei = 0; const float* w = 0;
    const float* W1 = 0; const float* b1 = 0; const float* W2 = 0; const float* b2 = 0;
    for (int i = 0; i < n_in; i++) {
        int sz = in_sizes[i];
        if      (sz == NN)     x  = (const float*)d_in[i];
        else if (sz == 2 * NE) ei = d_in[i];
        else if (sz == NE)     w  = (const float*)d_in[i];
        else if (sz == 32)     W2 = (const float*)d_in[i];
        else if (sz == 2)      b2 = (const float*)d_in[i];
        else if (sz == 16) {
            if (!W1) W1 = (const float*)d_in[i];
            else     b1 = (const float*)d_in[i];
        }
    }

    const int TB = 256;
    const int GN = (NN + TB - 1) / TB;
    const int GE = (NE / 8 + TB - 1) / TB;   // NE % 8 == 0

    k_init      <<<GN, TB>>>((const unsigned int*)ei);
    k_deg       <<<GE, TB>>>(ei, w);
    k_dinv      <<<GN, TB>>>(x);
    k_scatter1  <<<GE, TB>>>(ei);
    k_node_mid  <<<GN, TB>>>(x, W1, b1, W2);
    k_scatter2  <<<GE, TB>>>(ei);
    k_out       <<<GN, TB>>>(b2, (float2*)d_out);
}

// round 16
// speedup vs baseline: 1.3137x; 1.0727x over previous
#include <cuda_runtime.h>
#include <cuda_fp16.h>
#include <math.h>

#define NN 100000
#define NE 3200000

// Scratch (static device globals — no allocs anywhere)
__device__ int    g_src[NE];    // int64-fallback only
__device__ int    g_dst[NE];    // int64-fallback only
__device__ __half g_w16[NE];    // fp16 weight cache (6.4MB)
__device__ float  g_deg[NN];
__device__ float  g_dinv[NN];
__device__ __half g_p1[NN];     // half(dinv * x)
__device__ float  g_acc1[NN];   // zeroed in k_init
__device__ __half g_gd[NN];     // half(dinv * (g1-g0))
__device__ float  g_acc2[NN];   // seeded by store in k_node_mid
__device__ unsigned g_hi_or;    // 0 => int64 edge_index

__device__ __forceinline__ int clampn(int v) { return min(max(v, 0), NN - 1); }

__device__ __forceinline__ float ldg_h_pin(const __half* p) {
    unsigned short u;
    asm volatile("ld.global.nc.L1::evict_last.u16 %0, [%1];" : "=h"(u) : "l"(p));
    return __half2float(__ushort_as_half(u));
}

// ---------------- node init (deg=1, acc1=0) + dtype probe -------------------
__global__ void k_init(const unsigned int* __restrict__ ei32) {
    int n = blockIdx.x * blockDim.x + threadIdx.x;
    if (n < NN) { g_deg[n] = 1.0f; g_acc1[n] = 0.0f; }
    if (blockIdx.x == 0) {   // block-local probe, single clean store (no reset race)
        __shared__ unsigned s_or;
        if (threadIdx.x == 0) s_or = 0u;
        __syncthreads();
        unsigned v = 0u;
        #pragma unroll
        for (int k = 0; k < 8; k++) v |= ei32[2 * (threadIdx.x * 8 + k) + 1];
        #pragma unroll
        for (int off = 16; off > 0; off >>= 1)
            v |= __shfl_xor_sync(0xFFFFFFFFu, v, off);
        if ((threadIdx.x & 31) == 0 && v) atomicOr(&s_or, v);
        __syncthreads();
        if (threadIdx.x == 0) g_hi_or = s_or;
    }
}

// ------- edge: degree REDs + fp16 weight cache. Pre-sync: input streams +
// w16 store (touches nothing k_init writes). Post-sync: REDs into g_deg. -----
__global__ void k_deg(const void* __restrict__ eiv,
                      const float* __restrict__ w) {
    int e = (blockIdx.x * blockDim.x + threadIdx.x) * 8;
    bool valid = (e < NE);
    float4 wa, wb; int4 da, db;
    if (valid) {
        wa = __ldcs((const float4*)(w + e));
        wb = __ldcs((const float4*)(w + e + 4));
        __half2 h0 = __floats2half2_rn(wa.x, wa.y);
        __half2 h1 = __floats2half2_rn(wa.z, wa.w);
        __half2 h2 = __floats2half2_rn(wb.x, wb.y);
        __half2 h3 = __floats2half2_rn(wb.z, wb.w);
        *(uint4*)(g_w16 + e) = make_uint4(*(unsigned*)&h0, *(unsigned*)&h1,
                                          *(unsigned*)&h2, *(unsigned*)&h3);
        const int* dp = (const int*)eiv + NE;     // int32 interpretation, in-bounds either way
        da = __ldcs((const int4*)(dp + e));
        db = __ldcs((const int4*)(dp + e + 4));
    }
    cudaGridDependencySynchronize();              // wait: k_init's deg=1 visible
    if (!valid) return;
    if (g_hi_or != 0u) {                          // int32 payload
        atomicAdd(&g_deg[clampn(da.x)], wa.x);
        atomicAdd(&g_deg[clampn(da.y)], wa.y);
        atomicAdd(&g_deg[clampn(da.z)], wa.z);
        atomicAdd(&g_deg[clampn(da.w)], wa.w);
        atomicAdd(&g_deg[clampn(db.x)], wb.x);
        atomicAdd(&g_deg[clampn(db.y)], wb.y);
        atomicAdd(&g_deg[clampn(db.z)], wb.z);
        atomicAdd(&g_deg[clampn(db.w)], wb.w);
    } else {                                      // int64 fallback: narrow + stash
        const long long* ei = (const long long*)eiv;
        #pragma unroll
        for (int k = 0; k < 8; k++) {
            int s = clampn((int)ei[e + k]);
            int d = clampn((int)ei[NE + e + k]);
            float wk = (k < 4) ? (&wa.x)[k] : (&wb.x)[k - 4];
            g_src[e + k] = s;  g_dst[e + k] = d;
            atomicAdd(&g_deg[d], wk);
        }
    }
}

// --------- node: dinv + pre-scaled feature. Pre-sync: x. Post: deg. ---------
__global__ void k_dinv(const float* __restrict__ x) {
    int n = blockIdx.x * blockDim.x + threadIdx.x;
    float xv = (n < NN) ? __ldcs(&x[n]) : 0.0f;
    cudaGridDependencySynchronize();
    if (n < NN) {
        float d  = g_deg[n];
        float di = (d > 0.0f) ? rsqrtf(d) : 0.0f;
        g_dinv[n] = di;
        g_p1[n]   = __float2half_rn(di * xv);
    }
}

// ---- edge scatter1. Pre-sync: all streams (inputs + w16 from 2-back deg).
// Post-sync: p1 gathers (immediate pred) + acc1 REDs. ------------------------
__global__ void k_scatter1(const void* __restrict__ eiv) {
    int e = (blockIdx.x * blockDim.x + threadIdx.x) * 8;
    bool valid = (e < NE);
    int4 sa, sb, da, db; uint4 wp;
    const int* sp32 = (const int*)eiv;
    if (valid) {
        sa = __ldcs((const int4*)(sp32 + e));
        sb = __ldcs((const int4*)(sp32 + e + 4));
        da = __ldcs((const int4*)(sp32 + NE + e));
        db = __ldcs((const int4*)(sp32 + NE + e + 4));
        wp = __ldcs((const uint4*)(g_w16 + e));   // written 2 kernels back: safe
    }
    cudaGridDependencySynchronize();              // wait: k_dinv's p1 visible
    if (!valid) return;
    if (g_hi_or == 0u) {                          // int64 fallback: reload stash
        sa = *(const int4*)(g_src + e);  sb = *(const int4*)(g_src + e + 4);
        da = *(const int4*)(g_dst + e);  db = *(const int4*)(g_dst + e + 4);
    }
    float2 w01 = __half22float2(*(__half2*)&wp.x);
    float2 w23 = __half22float2(*(__half2*)&wp.y);
    float2 w45 = __half22float2(*(__half2*)&wp.z);
    float2 w67 = __half22float2(*(__half2*)&wp.w);
    float p0 = ldg_h_pin(&g_p1[clampn(sa.x)]);
    float p1 = ldg_h_pin(&g_p1[clampn(sa.y)]);
    float p2 = ldg_h_pin(&g_p1[clampn(sa.z)]);
    float p3 = ldg_h_pin(&g_p1[clampn(sa.w)]);
    float p4 = ldg_h_pin(&g_p1[clampn(sb.x)]);
    float p5 = ldg_h_pin(&g_p1[clampn(sb.y)]);
    float p6 = ldg_h_pin(&g_p1[clampn(sb.z)]);
    float p7 = ldg_h_pin(&g_p1[clampn(sb.w)]);
    atomicAdd(&g_acc1[clampn(da.x)], w01.x * p0);
    atomicAdd(&g_acc1[clampn(da.y)], w01.y * p1);
    atomicAdd(&g_acc1[clampn(da.z)], w23.x * p2);
    atomicAdd(&g_acc1[clampn(da.w)], w23.y * p3);
    atomicAdd(&g_acc1[clampn(db.x)], w45.x * p4);
    atomicAdd(&g_acc1[clampn(db.y)], w45.y * p5);
    atomicAdd(&g_acc1[clampn(db.z)], w67.x * p6);
    atomicAdd(&g_acc1[clampn(db.w)], w67.y * p7);
}

// ---- node mid. Pre-sync: x, dinv (2 back), weights. Post-sync: acc1. -------
__global__ void k_node_mid(const float* __restrict__ x,
                           const float* __restrict__ W1,
                           const float* __restrict__ b1,
                           const float* __restrict__ W2) {
    int n = blockIdx.x * blockDim.x + threadIdx.x;
    float xv = 0.0f, di = 0.0f;
    if (n < NN) { xv = __ldcs(&x[n]); di = g_dinv[n]; }   // dinv: 2 back, safe
    cudaGridDependencySynchronize();                       // wait: acc1 complete
    if (n < NN) {
        float sv = di * (g_acc1[n] + di * xv);
        float g0 = 0.0f, g1 = 0.0f;
        #pragma unroll
        for (int j = 0; j < 16; j++) {
            float h = fmaxf(fmaf(sv, __ldg(&W1[j]), __ldg(&b1[j])), 0.0f);
            g0 = fmaf(h, __ldg(&W2[2 * j    ]), g0);
            g1 = fmaf(h, __ldg(&W2[2 * j + 1]), g1);
        }
        float gd = di * (g1 - g0);
        g_gd[n]   = __float2half_rn(gd);
        g_acc2[n] = gd;                // self-loop seed
    }
}

// ---- edge scatter2. Pre-sync: streams. Post-sync: gd gathers + acc2 REDs. --
__global__ void k_scatter2(const void* __restrict__ eiv) {
    int e = (blockIdx.x * blockDim.x + threadIdx.x) * 8;
    bool valid = (e < NE);
    int4 sa, sb, da, db; uint4 wp;
    const int* sp32 = (const int*)eiv;
    if (valid) {
        sa = __ldcs((const int4*)(sp32 + e));
        sb = __ldcs((const int4*)(sp32 + e + 4));
        da = __ldcs((const int4*)(sp32 + NE + e));
        db = __ldcs((const int4*)(sp32 + NE + e + 4));
        wp = __ldcs((const uint4*)(g_w16 + e));
    }
    cudaGridDependencySynchronize();              // wait: gd + acc2 seed visible
    if (!valid) return;
    if (g_hi_or == 0u) {
        sa = *(const int4*)(g_src + e);  sb = *(const int4*)(g_src + e + 4);
        da = *(const int4*)(g_dst + e);  db = *(const int4*)(g_dst + e + 4);
    }
    float2 w01 = __half22float2(*(__half2*)&wp.x);
    float2 w23 = __half22float2(*(__half2*)&wp.y);
    float2 w45 = __half22float2(*(__half2*)&wp.z);
    float2 w67 = __half22float2(*(__half2*)&wp.w);
    float v0 = ldg_h_pin(&g_gd[clampn(sa.x)]);
    float v1 = ldg_h_pin(&g_gd[clampn(sa.y)]);
    float v2 = ldg_h_pin(&g_gd[clampn(sa.z)]);
    float v3 = ldg_h_pin(&g_gd[clampn(sa.w)]);
    float v4 = ldg_h_pin(&g_gd[clampn(sb.x)]);
    float v5 = ldg_h_pin(&g_gd[clampn(sb.y)]);
    float v6 = ldg_h_pin(&g_gd[clampn(sb.z)]);
    float v7 = ldg_h_pin(&g_gd[clampn(sb.w)]);
    atomicAdd(&g_acc2[clampn(da.x)], w01.x * v0);
    atomicAdd(&g_acc2[clampn(da.y)], w01.y * v1);
    atomicAdd(&g_acc2[clampn(da.z)], w23.x * v2);
    atomicAdd(&g_acc2[clampn(da.w)], w23.y * v3);
    atomicAdd(&g_acc2[clampn(db.x)], w45.x * v4);
    atomicAdd(&g_acc2[clampn(db.y)], w45.y * v5);
    atomicAdd(&g_acc2[clampn(db.z)], w67.x * v6);
    atomicAdd(&g_acc2[clampn(db.w)], w67.y * v7);
}

// ---- out. Pre-sync: dinv (far back) + b2. Post-sync: acc2. -----------------
__global__ void k_out(const float* __restrict__ b2, float2* __restrict__ out) {
    int n = blockIdx.x * blockDim.x + threadIdx.x;
    float di = 0.0f, bd = 0.0f;
    if (n < NN) { di = g_dinv[n]; bd = __ldg(&b2[1]) - __ldg(&b2[0]); }
    cudaGridDependencySynchronize();
    if (n < NN) {
        float v  = di * g_acc2[n] + bd;   // v1 - v0
        float o0 = (v > 0.0f) ? (-v - log1pf(expf(-v))) : (-log1pf(expf(v)));
        out[n] = make_float2(o0, o0 + v);
    }
}

// ---------------- host: PDL launches on the capture stream ------------------
static inline void launch_pdl(const void* fn, int grid, int tb, void** args) {
    cudaLaunchConfig_t cfg = {};
    cfg.gridDim  = dim3((unsigned)grid, 1, 1);
    cfg.blockDim = dim3((unsigned)tb, 1, 1);
    cfg.stream   = 0;    // legacy default stream (capture maps it)
    cudaLaunchAttribute a[1];
    a[0].id = cudaLaunchAttributeProgrammaticStreamSerialization;
    a[0].val.programmaticStreamSerializationAllowed = 1;
    cfg.attrs = a; cfg.numAttrs = 1;
    cudaLaunchKernelExC(&cfg, fn, args);
}

extern "C" void kernel_launch(void* const* d_in, const int* in_sizes, int n_in,
                              void* d_out, int out_size) {
    const float* x = 0; const void* ei = 0; const float* w = 0;
    const float* W1 = 0; const float* b1 = 0; const float* W2 = 0; const float* b2 = 0;
    for (int i = 0; i < n_in; i++) {
        int sz = in_sizes[i];
        if      (sz == NN)     x  = (const float*)d_in[i];
        else if (sz == 2 * NE) ei = d_in[i];
        else if (sz == NE)     w  = (const float*)d_in[i];
        else if (sz == 32)     W2 = (const float*)d_in[i];
        else if (sz == 2)      b2 = (const float*)d_in[i];
        else if (sz == 16) {
            if (!W1) W1 = (const float*)d_in[i];
            else     b1 = (const float*)d_in[i];
        }
    }
    float2* out = (float2*)d_out;

    const int TB = 256;
    const int GN = (NN + TB - 1) / TB;
    const int GE = (NE / 8 + TB - 1) / TB;   // NE % 8 == 0

    const unsigned int* ei32 = (const unsigned int*)ei;
    void* a_init[] = { (void*)&ei32 };
    void* a_deg [] = { (void*)&ei, (void*)&w };
    void* a_dinv[] = { (void*)&x };
    void* a_sc1 [] = { (void*)&ei };
    void* a_mid [] = { (void*)&x, (void*)&W1, (void*)&b1, (void*)&W2 };
    void* a_sc2 [] = { (void*)&ei };
    void* a_out [] = { (void*)&b2, (void*)&out };

    launch_pdl((const void*)k_init,     GN, TB, a_init);
    launch_pdl((const void*)k_deg,      GE, TB, a_deg);
    launch_pdl((const void*)k_dinv,     GN, TB, a_dinv);
    launch_pdl((const void*)k_scatter1, GE, TB, a_sc1);
    launch_pdl((const void*)k_node_mid, GN, TB, a_mid);
    launch_pdl((const void*)k_scatter2, GE, TB, a_sc2);
    launch_pdl((const void*)k_out,      GN, TB, a_out);
}